// round 13
// baseline (speedup 1.0000x reference)
#include <cuda_runtime.h>
#include <cstdint>

#define BSZ 4
#define D 16
#define MDIM 32
#define LTOT 81

#define ADD4(a, v) do { (a).x += (v).x; (a).y += (v).y; (a).z += (v).z; (a).w += (v).w; } while (0)

// Q[slab][jj][m], slab=(b,p1,p2) 0..1023, jj=j3*3+j4. 1.18 MB.
__device__ float g_Q[BSZ * D * D * 9 * MDIM];
__device__ float g_H[BSZ * LTOT];

__device__ __forceinline__ uint32_t smem_u32(const void* p) {
    uint32_t a;
    asm("{ .reg .u64 t; cvta.to.shared.u64 t, %1; cvt.u32.u64 %0, t; }" : "=r"(a) : "l"(p));
    return a;
}
__device__ __forceinline__ void mbar_init(uint32_t mbar, uint32_t cnt) {
    asm volatile("mbarrier.init.shared.b64 [%0], %1;" :: "r"(mbar), "r"(cnt) : "memory");
}
__device__ __forceinline__ void mbar_expect_tx(uint32_t mbar, uint32_t bytes) {
    asm volatile("mbarrier.arrive.expect_tx.shared.b64 _, [%0], %1;" :: "r"(mbar), "r"(bytes) : "memory");
}
__device__ __forceinline__ void mbar_wait(uint32_t mbar, uint32_t parity) {
    asm volatile(
        "{\n\t.reg .pred P;\n\t"
        "WAIT_%=:\n\t"
        "mbarrier.try_wait.parity.acquire.cta.shared::cta.b64 P, [%0], %1, 0x989680;\n\t"
        "@!P bra WAIT_%=;\n\t}"
        :: "r"(mbar), "r"(parity) : "memory");
}
__device__ __forceinline__ void bulk_g2s(uint32_t dst, const void* src, uint32_t bytes, uint32_t mbar) {
    asm volatile(
        "cp.async.bulk.shared::cta.global.mbarrier::complete_tx::bytes [%0], [%1], %2, [%3];"
        :: "r"(dst), "l"(src), "r"(bytes), "r"(mbar) : "memory");
}

// ---------------------------------------------------------------------------
// Pass 1: ONE slab (32 KB) per CTA, 1024 CTAs. All 4 chunks issued in the
// prologue (4-stage ring, no refills, no mid-loop barriers). Thread = (m4,p4).
// Chunk i covers p3 = 4i..4i+3 (compile-time classes). One epilogue reduces
// p4 -> j4 classes into g_Q[slab][jj][m].
// Position weight: p in class (p-1)%3 (if p>=1) and p%3 (if p<=14).
// ---------------------------------------------------------------------------
#define CHUNK_BYTES 8192
__global__ void __launch_bounds__(128) pass1_kernel(const char* __restrict__ arr) {
    __shared__ __align__(16) float buf[4][4 * 16 * 32];   // 4 x 8KB ring
    __shared__ float4 S[16][3][8];                         // [p4][j3][m4] 6KB
    __shared__ __align__(8) unsigned long long mbar[4];

    const int t  = threadIdx.x;
    const int m4 = t & 7;
    const int p4 = t >> 3;          // 0..15

    uint32_t mb[4];
#pragma unroll
    for (int q = 0; q < 4; ++q) mb[q] = smem_u32(&mbar[q]);

    if (t == 0) {
#pragma unroll
        for (int q = 0; q < 4; ++q) mbar_init(mb[q], 1);
    }
    __syncthreads();

    const int slab = blockIdx.x;
    const char* __restrict__ src = arr + (size_t)slab * 32768;

    // Prologue: whole slab requested immediately.
    if (t == 0) {
#pragma unroll
        for (int q = 0; q < 4; ++q) {
            mbar_expect_tx(mb[q], CHUNK_BYTES);
            bulk_g2s(smem_u32(&buf[q][0]), src + q * CHUNK_BYTES, CHUNK_BYTES, mb[q]);
        }
    }

    float4 t0 = {0.f,0.f,0.f,0.f}, t1 = t0, t2 = t0;

#pragma unroll
    for (int i = 0; i < 4; ++i) {
        mbar_wait(mb[i], 0u);

        const float4* __restrict__ bp = (const float4*)(&buf[i][0]) + p4 * 8 + m4;
#pragma unroll
        for (int k = 0; k < 4; ++k) {
            const int p3 = i * 4 + k;              // compile-time
            float4 v = bp[k * 128];
            if (p3 >= 1) {
                const int ja = (p3 - 1) % 3;
                if (ja == 0) ADD4(t0, v); else if (ja == 1) ADD4(t1, v); else ADD4(t2, v);
            }
            if (p3 <= 14) {
                const int jb = p3 % 3;
                if (jb == 0) ADD4(t0, v); else if (jb == 1) ADD4(t1, v); else ADD4(t2, v);
            }
        }
    }

    S[p4][0][m4] = t0;
    S[p4][1][m4] = t1;
    S[p4][2][m4] = t2;
    __syncthreads();

    if (t < 72) {                  // t = jj*8 + mm : reduce p4 -> j4 classes
        const int mm = t & 7;
        const int jj = t >> 3;     // j3*3 + j4
        const int j4 = jj % 3;
        const int j3 = jj / 3;
        float4 qv = {0.f,0.f,0.f,0.f};
#pragma unroll
        for (int u = 0; u < 10; ++u) {
            const int p = 3 * (u >> 1) + j4 + (u & 1);
            ADD4(qv, S[p][j3][mm]);
        }
        ((float4*)g_Q)[slab * 72 + jj * 8 + mm] = qv;
    }

    // All g_Q writes for this CTA are done: release to dependent grid.
    cudaTriggerProgrammaticLaunchCompletion();
}

// ---------------------------------------------------------------------------
// Pass 2 (PDL consumer): block (c, b), 128 threads.
// Prologue (independent of g_Q): E[c,m] = sum_n Bbasis[c,n]*M[n,m].
// Then cudaGridDependencySynchronize(), then G from g_Q, H[b,c] out.
// ---------------------------------------------------------------------------
__global__ void __launch_bounds__(128) pass2_kernel(const float* __restrict__ Mmat,
                                                    const float* __restrict__ Bbasis) {
    __shared__ float E_s[32];
    __shared__ float part[4][32];

    const int c  = blockIdx.x;   // 0..80
    const int b  = blockIdx.y;   // 0..3
    const int t  = threadIdx.x;
    const int lane = t & 31;
    const int wp   = t >> 5;

    const int j4 = c % 3;
    const int j3 = (c / 3) % 3;
    const int j2 = (c / 9) % 3;
    const int j1 = c / 27;
    const int jj = j3 * 3 + j4;

    // ---- prologue: overlaps with pass1 execution ----
    if (t < 32) {
        float e = 0.f;
#pragma unroll
        for (int n = 0; n < MDIM; ++n)
            e += Bbasis[c * MDIM + n] * Mmat[n * MDIM + t];
        E_s[t] = e;
    }

    // ---- wait for pass1's g_Q ----
    cudaGridDependencySynchronize();

    float g = 0.f;
#pragma unroll
    for (int k = wp; k < 20; k += 4) {       // 5 independent load groups per warp
        const int i  = k >> 1;               // p1-window index 0..9
        const int hh = k & 1;                // p2 half 0..1 (5 windows each)
        const int p1 = 3 * (i >> 1) + j1 + (i & 1);
#pragma unroll
        for (int u = 0; u < 5; ++u) {
            const int i2 = hh * 5 + u;
            const int p2 = 3 * (i2 >> 1) + j2 + (i2 & 1);
            g += g_Q[(((b * D + p1) * D + p2) * 9 + jj) * MDIM + lane];
        }
    }
    part[wp][lane] = g;
    __syncthreads();

    if (wp == 0) {
        float G = part[0][lane] + part[1][lane] + part[2][lane] + part[3][lane];
        float h = E_s[lane] * G;
#pragma unroll
        for (int o = 16; o; o >>= 1)
            h += __shfl_xor_sync(0xffffffffu, h, o);
        if (lane == 0) g_H[b * LTOT + c] = h;
    }

    cudaTriggerProgrammaticLaunchCompletion();
}

// ---------------------------------------------------------------------------
// Pass 3 (PDL consumer): stage Acoeff during pass2, then finish.
// out[b,n] = K * sum_c H[b,c] * Acoeff[n,c],  K = 1/(16 * 15^4)
// ---------------------------------------------------------------------------
__global__ void __launch_bounds__(128) pass3_kernel(const float* __restrict__ Acoeff,
                                                    float* __restrict__ out) {
    __shared__ float A_s[MDIM * LTOT];   // [n][c] 10.4 KB

    const int t = threadIdx.x;
    for (int i = t; i < MDIM * LTOT; i += 128)
        A_s[i] = Acoeff[i];
    __syncthreads();

    cudaGridDependencySynchronize();

    const int b = t >> 5;
    const int n = t & 31;
    const float K = 1.0f / (16.0f * 50625.0f);
    float s = 0.f;
#pragma unroll
    for (int c = 0; c < LTOT; ++c)
        s += g_H[b * LTOT + c] * A_s[n * LTOT + c];
    out[b * MDIM + n] = s * K;
}

extern "C" void kernel_launch(void* const* d_in, const int* in_sizes, int n_in,
                              void* d_out, int out_size) {
    const char* arr     = (const char*)d_in[0];    // [4,16,16,16,16,32] f32
    const float* Mmat   = (const float*)d_in[1];   // [32,32]
    const float* Acoeff = (const float*)d_in[2];   // [32,81]
    const float* Bbasis = (const float*)d_in[3];   // [81,32]
    float* out = (float*)d_out;                    // [4,32]

    pass1_kernel<<<1024, 128>>>(arr);              // 1 slab per CTA

    cudaLaunchAttribute attr[1];
    attr[0].id = cudaLaunchAttributeProgrammaticStreamSerialization;
    attr[0].val.programmaticStreamSerializationAllowed = 1;

    {   // pass2 with PDL
        cudaLaunchConfig_t cfg = {};
        cfg.gridDim  = dim3(LTOT, BSZ, 1);
        cfg.blockDim = dim3(128, 1, 1);
        cfg.dynamicSmemBytes = 0;
        cfg.stream = 0;
        cfg.attrs = attr;
        cfg.numAttrs = 1;
        cudaLaunchKernelEx(&cfg, pass2_kernel, Mmat, Bbasis);
    }
    {   // pass3 with PDL
        cudaLaunchConfig_t cfg = {};
        cfg.gridDim  = dim3(1, 1, 1);
        cfg.blockDim = dim3(128, 1, 1);
        cfg.dynamicSmemBytes = 0;
        cfg.stream = 0;
        cfg.attrs = attr;
        cfg.numAttrs = 1;
        cudaLaunchKernelEx(&cfg, pass3_kernel, Acoeff, out);
    }
}

// round 14
// speedup vs baseline: 1.1575x; 1.1575x over previous
#include <cuda_runtime.h>
#include <cstdint>

#define BSZ 4
#define D 16
#define MDIM 32
#define LTOT 81

#define ADD4(a, v) do { (a).x += (v).x; (a).y += (v).y; (a).z += (v).z; (a).w += (v).w; } while (0)

// Q[slab][jj][m], slab=(b,p1,p2) 0..1023, jj=j3*3+j4. 1.18 MB.
__device__ float g_Q[BSZ * D * D * 9 * MDIM];
__device__ float g_H[BSZ * LTOT];

__device__ __forceinline__ uint32_t smem_u32(const void* p) {
    uint32_t a;
    asm("{ .reg .u64 t; cvta.to.shared.u64 t, %1; cvt.u32.u64 %0, t; }" : "=r"(a) : "l"(p));
    return a;
}
__device__ __forceinline__ void mbar_init(uint32_t mbar, uint32_t cnt) {
    asm volatile("mbarrier.init.shared.b64 [%0], %1;" :: "r"(mbar), "r"(cnt) : "memory");
}
__device__ __forceinline__ void mbar_expect_tx(uint32_t mbar, uint32_t bytes) {
    asm volatile("mbarrier.arrive.expect_tx.shared.b64 _, [%0], %1;" :: "r"(mbar), "r"(bytes) : "memory");
}
__device__ __forceinline__ void mbar_wait(uint32_t mbar, uint32_t parity) {
    asm volatile(
        "{\n\t.reg .pred P;\n\t"
        "WAIT_%=:\n\t"
        "mbarrier.try_wait.parity.acquire.cta.shared::cta.b64 P, [%0], %1, 0x989680;\n\t"
        "@!P bra WAIT_%=;\n\t}"
        :: "r"(mbar), "r"(parity) : "memory");
}
__device__ __forceinline__ void bulk_g2s(uint32_t dst, const void* src, uint32_t bytes, uint32_t mbar) {
    asm volatile(
        "cp.async.bulk.shared::cta.global.mbarrier::complete_tx::bytes [%0], [%1], %2, [%3];"
        :: "r"(dst), "l"(src), "r"(bytes), "r"(mbar) : "memory");
}
__device__ __forceinline__ void fence_proxy_async_cta() {
    asm volatile("fence.proxy.async.shared::cta;" ::: "memory");
}

// ---------------------------------------------------------------------------
// Pass 1: CTA k owns slabs 2k, 2k+1 = 64 KB = 4 chunks of 16 KB.
// 3-stage ring (48 KB): 3 chunks issued in prologue, chunk 3 refills stage 0
// after chunk 0 is consumed (single refill barrier). Thread = (m4, p4).
// Chunk i: slab = slab0 + (i>>1), p3 = (i&1)*8 + k, k=0..7 (compile-time).
// Epilogues after chunks 1 and 3 reduce p4 -> j4 classes into g_Q.
// Position weight: p in class (p-1)%3 (if p>=1) and p%3 (if p<=14).
// ---------------------------------------------------------------------------
#define CHUNK_BYTES 16384
__global__ void __launch_bounds__(128) pass1_kernel(const char* __restrict__ arr) {
    __shared__ __align__(16) float buf[3][8 * 16 * 32];   // 3 x 16KB ring
    __shared__ float4 S[16][3][8];                          // [p4][j3][m4] 6KB
    __shared__ __align__(8) unsigned long long mbar[3];

    const int t  = threadIdx.x;
    const int m4 = t & 7;
    const int p4 = t >> 3;          // 0..15

    uint32_t mb[3];
#pragma unroll
    for (int q = 0; q < 3; ++q) mb[q] = smem_u32(&mbar[q]);

    if (t == 0) {
#pragma unroll
        for (int q = 0; q < 3; ++q) mbar_init(mb[q], 1);
    }
    __syncthreads();

    const int slab0 = blockIdx.x * 2;
    const char* __restrict__ src0 = arr + (size_t)slab0 * 32768;

    // Prologue: 3 of 4 chunks (48 KB) in flight immediately.
    if (t == 0) {
#pragma unroll
        for (int q = 0; q < 3; ++q) {
            mbar_expect_tx(mb[q], CHUNK_BYTES);
            bulk_g2s(smem_u32(&buf[q][0]), src0 + q * CHUNK_BYTES, CHUNK_BYTES, mb[q]);
        }
    }

    float4 t0 = {0.f,0.f,0.f,0.f}, t1 = t0, t2 = t0;

#pragma unroll
    for (int i = 0; i < 4; ++i) {
        const int stage  = (i < 3) ? i : 0;
        const int parity = (i < 3) ? 0 : 1;
        mbar_wait(mb[stage], (uint32_t)parity);

        const float4* __restrict__ bp = (const float4*)(&buf[stage][0]) + p4 * 8 + m4;
#pragma unroll
        for (int k = 0; k < 8; ++k) {
            const int p3 = (i & 1) * 8 + k;        // compile-time
            float4 v = bp[k * 128];
            if (p3 >= 1) {
                const int ja = (p3 - 1) % 3;
                if (ja == 0) ADD4(t0, v); else if (ja == 1) ADD4(t1, v); else ADD4(t2, v);
            }
            if (p3 <= 14) {
                const int jb = p3 % 3;
                if (jb == 0) ADD4(t0, v); else if (jb == 1) ADD4(t1, v); else ADD4(t2, v);
            }
        }

        if (i == 0) {                // refill stage 0 with chunk 3
            __syncthreads();         // all reads of stage 0 complete
            if (t == 0) {
                fence_proxy_async_cta();
                mbar_expect_tx(mb[0], CHUNK_BYTES);
                bulk_g2s(smem_u32(&buf[0][0]),
                         src0 + 3 * CHUNK_BYTES, CHUNK_BYTES, mb[0]);
            }
        }

        if (i == 1 || i == 3) {      // epilogue for slab i>>1
            const int slab = slab0 + (i >> 1);
            __syncthreads();         // prior S use (reduce) finished
            S[p4][0][m4] = t0;
            S[p4][1][m4] = t1;
            S[p4][2][m4] = t2;
            __syncthreads();

            if (t < 72) {            // t = jj*8 + mm : reduce p4 -> j4 classes
                const int mm = t & 7;
                const int jj = t >> 3;   // j3*3 + j4
                const int j4 = jj % 3;
                const int j3 = jj / 3;
                float4 qv = {0.f,0.f,0.f,0.f};
#pragma unroll
                for (int u = 0; u < 10; ++u) {
                    const int p = 3 * (u >> 1) + j4 + (u & 1);
                    ADD4(qv, S[p][j3][mm]);
                }
                ((float4*)g_Q)[slab * 72 + jj * 8 + mm] = qv;
            }
            t0 = make_float4(0.f, 0.f, 0.f, 0.f);
            t1 = t0;
            t2 = t0;
        }
    }

    // All g_Q writes for this CTA are done: release to dependent grid.
    cudaTriggerProgrammaticLaunchCompletion();
}

// ---------------------------------------------------------------------------
// Pass 2 (PDL consumer): block (c, b), 128 threads.
// Prologue (independent of g_Q): E[c,m] = sum_n Bbasis[c,n]*M[n,m].
// Then cudaGridDependencySynchronize(), then G from g_Q, H[b,c] out.
// ---------------------------------------------------------------------------
__global__ void __launch_bounds__(128) pass2_kernel(const float* __restrict__ Mmat,
                                                    const float* __restrict__ Bbasis) {
    __shared__ float E_s[32];
    __shared__ float part[4][32];

    const int c  = blockIdx.x;   // 0..80
    const int b  = blockIdx.y;   // 0..3
    const int t  = threadIdx.x;
    const int lane = t & 31;
    const int wp   = t >> 5;

    const int j4 = c % 3;
    const int j3 = (c / 3) % 3;
    const int j2 = (c / 9) % 3;
    const int j1 = c / 27;
    const int jj = j3 * 3 + j4;

    // ---- prologue: overlaps with pass1 execution ----
    if (t < 32) {
        float e = 0.f;
#pragma unroll
        for (int n = 0; n < MDIM; ++n)
            e += Bbasis[c * MDIM + n] * Mmat[n * MDIM + t];
        E_s[t] = e;
    }

    // ---- wait for pass1's g_Q ----
    cudaGridDependencySynchronize();

    float g = 0.f;
#pragma unroll
    for (int k = wp; k < 20; k += 4) {       // 5 independent load groups per warp
        const int i  = k >> 1;               // p1-window index 0..9
        const int hh = k & 1;                // p2 half 0..1 (5 windows each)
        const int p1 = 3 * (i >> 1) + j1 + (i & 1);
#pragma unroll
        for (int u = 0; u < 5; ++u) {
            const int i2 = hh * 5 + u;
            const int p2 = 3 * (i2 >> 1) + j2 + (i2 & 1);
            g += g_Q[(((b * D + p1) * D + p2) * 9 + jj) * MDIM + lane];
        }
    }
    part[wp][lane] = g;
    __syncthreads();

    if (wp == 0) {
        float G = part[0][lane] + part[1][lane] + part[2][lane] + part[3][lane];
        float h = E_s[lane] * G;
#pragma unroll
        for (int o = 16; o; o >>= 1)
            h += __shfl_xor_sync(0xffffffffu, h, o);
        if (lane == 0) g_H[b * LTOT + c] = h;
    }

    cudaTriggerProgrammaticLaunchCompletion();
}

// ---------------------------------------------------------------------------
// Pass 3 (PDL consumer): stage Acoeff during pass2, then finish.
// out[b,n] = K * sum_c H[b,c] * Acoeff[n,c],  K = 1/(16 * 15^4)
// ---------------------------------------------------------------------------
__global__ void __launch_bounds__(128) pass3_kernel(const float* __restrict__ Acoeff,
                                                    float* __restrict__ out) {
    __shared__ float A_s[MDIM * LTOT];   // [n][c] 10.4 KB

    const int t = threadIdx.x;
    for (int i = t; i < MDIM * LTOT; i += 128)
        A_s[i] = Acoeff[i];
    __syncthreads();

    cudaGridDependencySynchronize();

    const int b = t >> 5;
    const int n = t & 31;
    const float K = 1.0f / (16.0f * 50625.0f);
    float s = 0.f;
#pragma unroll
    for (int c = 0; c < LTOT; ++c)
        s += g_H[b * LTOT + c] * A_s[n * LTOT + c];
    out[b * MDIM + n] = s * K;
}

extern "C" void kernel_launch(void* const* d_in, const int* in_sizes, int n_in,
                              void* d_out, int out_size) {
    const char* arr     = (const char*)d_in[0];    // [4,16,16,16,16,32] f32
    const float* Mmat   = (const float*)d_in[1];   // [32,32]
    const float* Acoeff = (const float*)d_in[2];   // [32,81]
    const float* Bbasis = (const float*)d_in[3];   // [81,32]
    float* out = (float*)d_out;                    // [4,32]

    pass1_kernel<<<512, 128>>>(arr);               // 2 slabs per CTA

    cudaLaunchAttribute attr[1];
    attr[0].id = cudaLaunchAttributeProgrammaticStreamSerialization;
    attr[0].val.programmaticStreamSerializationAllowed = 1;

    {   // pass2 with PDL
        cudaLaunchConfig_t cfg = {};
        cfg.gridDim  = dim3(LTOT, BSZ, 1);
        cfg.blockDim = dim3(128, 1, 1);
        cfg.dynamicSmemBytes = 0;
        cfg.stream = 0;
        cfg.attrs = attr;
        cfg.numAttrs = 1;
        cudaLaunchKernelEx(&cfg, pass2_kernel, Mmat, Bbasis);
    }
    {   // pass3 with PDL
        cudaLaunchConfig_t cfg = {};
        cfg.gridDim  = dim3(1, 1, 1);
        cfg.blockDim = dim3(128, 1, 1);
        cfg.dynamicSmemBytes = 0;
        cfg.stream = 0;
        cfg.attrs = attr;
        cfg.numAttrs = 1;
        cudaLaunchKernelEx(&cfg, pass3_kernel, Acoeff, out);
    }
}